// round 16
// baseline (speedup 1.0000x reference)
#include <cuda_runtime.h>
#include <cuda_fp16.h>
#include <math_constants.h>
#include <cstdint>

// Pre-converted W (fp16). X is converted inside the gemm.
static __device__ __align__(16) __half g_Wh[256 * 1024];
// K|V projections, fp16: [B*N, 256]. K cols 0..127 pre-scaled by scale*log2e.
static __device__ __align__(16) __half g_KV[8 * 2048 * 256];
// Split-KV x4 partials: O~ in fp16, l in fp32.
static __device__ __align__(16) __half g_PO[4 * 8 * 2048 * 128];
static __device__ float g_Pl[4 * 8 * 2048];

// ---------------------------------------------------------------------------
// helpers
// ---------------------------------------------------------------------------
__device__ __forceinline__ float ex2(float v) {
    float r; asm("ex2.approx.f32 %0, %1;" : "=f"(r) : "f"(v));
    return r;
}
__device__ __forceinline__ void mma16h(float c[4], const uint32_t a[4],
                                       uint32_t b0, uint32_t b1) {
    asm volatile(
        "mma.sync.aligned.m16n8k16.row.col.f32.f16.f16.f32 "
        "{%0,%1,%2,%3}, {%4,%5,%6,%7}, {%8,%9}, {%0,%1,%2,%3};\n"
        : "+f"(c[0]), "+f"(c[1]), "+f"(c[2]), "+f"(c[3])
        : "r"(a[0]), "r"(a[1]), "r"(a[2]), "r"(a[3]), "r"(b0), "r"(b1));
}
__device__ __forceinline__ void ldmx4(uint32_t& r0, uint32_t& r1, uint32_t& r2,
                                      uint32_t& r3, uint32_t addr) {
    asm volatile("ldmatrix.sync.aligned.m8n8.x4.shared.b16 {%0,%1,%2,%3}, [%4];"
                 : "=r"(r0), "=r"(r1), "=r"(r2), "=r"(r3) : "r"(addr));
}
__device__ __forceinline__ void ldmx4t(uint32_t& r0, uint32_t& r1, uint32_t& r2,
                                       uint32_t& r3, uint32_t addr) {
    asm volatile("ldmatrix.sync.aligned.m8n8.x4.trans.shared.b16 {%0,%1,%2,%3}, [%4];"
                 : "=r"(r0), "=r"(r1), "=r"(r2), "=r"(r3) : "r"(addr));
}
__device__ __forceinline__ void cp16(uint32_t dst, const void* src) {
    asm volatile("cp.async.cg.shared.global [%0], [%1], 16;\n" :: "r"(dst), "l"(src));
}
__device__ __forceinline__ void cp_commit() { asm volatile("cp.async.commit_group;\n"); }
__device__ __forceinline__ void cp_wait0()  { asm volatile("cp.async.wait_group 0;\n"); }
__device__ __forceinline__ void cp_wait1()  { asm volatile("cp.async.wait_group 1;\n"); }

__device__ __forceinline__ uint32_t smem_u32(const void* p) {
    return (uint32_t)__cvta_generic_to_shared(p);
}
__device__ __forceinline__ uint32_t h2u(__half2 h) {
    return *reinterpret_cast<uint32_t*>(&h);
}

// ---------------------------------------------------------------------------
// Kernel 0: convert W -> fp16 (1 MB read).
// ---------------------------------------------------------------------------
__global__ __launch_bounds__(256) void convert_kernel(
    const float* __restrict__ wk, const float* __restrict__ wv)
{
    int wi = (blockIdx.x * 256 + threadIdx.x) * 8;
    int row = wi >> 10, col = wi & 1023;
    const float* src = (row < 128) ? wk + (size_t)row * 1024 + col
                                   : wv + (size_t)(row - 128) * 1024 + col;
    float4 v0 = *reinterpret_cast<const float4*>(src);
    float4 v1 = *reinterpret_cast<const float4*>(src + 4);
    uint4 H;
    H.x = h2u(__float22half2_rn(make_float2(v0.x, v0.y)));
    H.y = h2u(__float22half2_rn(make_float2(v0.z, v0.w)));
    H.z = h2u(__float22half2_rn(make_float2(v1.x, v1.y)));
    H.w = h2u(__float22half2_rn(make_float2(v1.z, v1.w)));
    *reinterpret_cast<uint4*>(g_Wh + wi) = H;
}

// ---------------------------------------------------------------------------
// Kernel 1: KV projection with fused X fp32->fp16 conversion (R15 winner).
// ---------------------------------------------------------------------------
static constexpr int GP        = 20;
static constexpr int XFP       = 36;
static constexpr int XF_WORDS  = 128 * XFP;
static constexpr int XH_OFF    = 3 * XF_WORDS;
static constexpr int XH_WORDS  = 128 * GP;
static constexpr int W_OFF     = XH_OFF + 2 * XH_WORDS;
static constexpr int W_WORDS   = 128 * GP;
static constexpr int GEMM_SMEM_BYTES = (W_OFF + 3 * W_WORDS) * 4;   // 106496

__global__ __launch_bounds__(256, 2) void kv_gemm_kernel(
    const float* __restrict__ x,
    const float* __restrict__ bk, const float* __restrict__ bv)
{
    extern __shared__ uint32_t su[];
    const uint32_t sb = smem_u32(su);
    const int j0 = blockIdx.x * 128;
    const int m0 = blockIdx.y * 128;
    const int tid  = threadIdx.x;
    const int lane = tid & 31;
    const int w    = tid >> 5;
    const int wm   = w & 3;
    const int wn   = w >> 2;
    const int g    = lane >> 2;
    const int t    = lane & 3;
    const int mat  = lane >> 3;
    const int mi   = lane & 7;

    auto fill = [&](int stage, int k0) {
        const uint32_t xf = sb + (uint32_t)(stage * XF_WORDS) * 4;
        #pragma unroll
        for (int i = 0; i < 4; ++i) {
            int slot = tid + i * 256, r = slot >> 3, c4 = slot & 7;
            cp16(xf + (uint32_t)(r * XFP + c4 * 4) * 4,
                 x + (size_t)(m0 + r) * 1024 + k0 + c4 * 4);
        }
        const uint32_t wb = sb + (uint32_t)(W_OFF + stage * W_WORDS) * 4;
        #pragma unroll
        for (int i = 0; i < 2; ++i) {
            int slot = tid + i * 256, r = slot >> 2, c = slot & 3;
            cp16(wb + (uint32_t)(r * GP + c * 4) * 4,
                 g_Wh + (size_t)(j0 + r) * 1024 + k0 + c * 8);
        }
        cp_commit();
    };

    auto cvt = [&](int stage, int buf) {
        const float* xf = reinterpret_cast<const float*>(su) + stage * XF_WORDS;
        uint32_t* xh = su + XH_OFF + buf * XH_WORDS;
        #pragma unroll
        for (int i = 0; i < 4; ++i) {
            int slot = tid + i * 256, r = slot >> 3, c4 = slot & 7;
            float4 v = *reinterpret_cast<const float4*>(xf + r * XFP + c4 * 4);
            uint2 H;
            H.x = h2u(__float22half2_rn(make_float2(v.x, v.y)));
            H.y = h2u(__float22half2_rn(make_float2(v.z, v.w)));
            *reinterpret_cast<uint2*>(xh + r * GP + c4 * 2) = H;
        }
    };

    fill(0, 0);
    fill(1, 32);
    cp_wait1();
    cvt(0, 0);
    __syncthreads();

    float acc[2][8][4] = {};

    for (int kt = 0; kt < 32; ++kt) {
        if (kt + 2 < 32) fill((kt + 2) % 3, (kt + 2) * 32);
        if (kt + 1 < 32) {
            if (kt + 2 < 32) cp_wait1(); else cp_wait0();
            cvt((kt + 1) % 3, (kt + 1) & 1);
        }

        const uint32_t xh  = sb + (uint32_t)(XH_OFF + (kt & 1) * XH_WORDS) * 4;
        const uint32_t whb = sb + (uint32_t)(W_OFF + (kt % 3) * W_WORDS) * 4;

        #pragma unroll
        for (int ks = 0; ks < 2; ++ks) {
            const int kca = ks * 8 + (mat >> 1) * 4;
            const int kcb = ks * 8 + (mat & 1) * 4;
            uint32_t a[2][4];
            #pragma unroll
            for (int mt = 0; mt < 2; ++mt) {
                int row = wm * 32 + mt * 16 + ((mat & 1) << 3) + mi;
                ldmx4(a[mt][0], a[mt][1], a[mt][2], a[mt][3],
                      xh + (uint32_t)(row * GP + kca) * 4);
            }
            #pragma unroll
            for (int np = 0; np < 4; ++np) {
                int row = wn * 64 + np * 16 + ((mat >> 1) << 3) + mi;
                uint32_t h0, h1, h2, h3;
                ldmx4(h0, h1, h2, h3, whb + (uint32_t)(row * GP + kcb) * 4);
                #pragma unroll
                for (int mt = 0; mt < 2; ++mt) {
                    mma16h(acc[mt][2 * np],     a[mt], h0, h1);
                    mma16h(acc[mt][2 * np + 1], a[mt], h2, h3);
                }
            }
        }
        __syncthreads();
    }

    const float SCL = 0.08838834764831845f * 1.4426950408889634f;
    #pragma unroll
    for (int mt = 0; mt < 2; ++mt) {
        int r0 = m0 + wm * 32 + mt * 16 + g;
        int r1 = r0 + 8;
        #pragma unroll
        for (int nt = 0; nt < 8; ++nt) {
            int col = j0 + wn * 64 + nt * 8 + 2 * t;
            bool isK = (col < 128);
            float b0 = isK ? bk[col]     : bv[col - 128];
            float b1 = isK ? bk[col + 1] : bv[col + 1 - 128];
            float v00 = acc[mt][nt][0] + b0, v01 = acc[mt][nt][1] + b1;
            float v10 = acc[mt][nt][2] + b0, v11 = acc[mt][nt][3] + b1;
            if (isK) { v00 *= SCL; v01 *= SCL; v10 *= SCL; v11 *= SCL; }
            __half2 h0 = __float22half2_rn(make_float2(v00, v01));
            __half2 h1 = __float22half2_rn(make_float2(v10, v11));
            *reinterpret_cast<__half2*>(g_KV + (size_t)r0 * 256 + col) = h0;
            *reinterpret_cast<__half2*>(g_KV + (size_t)r1 * 256 + col) = h1;
        }
    }
}

// ---------------------------------------------------------------------------
// Kernel 2: fused flash attention, split-KV x4 (512 keys / CTA, 8 tiles).
// Internals identical to the R11/R13 winner; only the KV range per CTA and
// the partial indexing changed. 256 CTAs -> 2 CTAs/SM for latency hiding.
// ---------------------------------------------------------------------------
__global__ __launch_bounds__(256, 2) void attn_kernel()
{
    extern __shared__ uint32_t su[];
    const int q0  = blockIdx.x * 256;
    const int kvi = blockIdx.y;           // 0..3
    const int b   = blockIdx.z;
    const int s0  = kvi * 512;
    const __half* KB = g_KV + (size_t)b * 2048 * 256;
    const int tid  = threadIdx.x;
    const int lane = tid & 31;
    const int w    = tid >> 5;
    const int g    = lane >> 2;
    const int t    = lane & 3;
    const int mat  = lane >> 3;
    const int mi   = lane & 7;
    const uint32_t swz = (uint32_t)mi << 2;

    const uint32_t sKq = smem_u32(su);
    const uint32_t sV  = sKq + 16384 * 4;

    #pragma unroll
    for (int i = 0; i < 16; ++i) {
        int slot = tid + i * 256, r = slot >> 4, ch = slot & 15;
        uint32_t dst = sKq + (uint32_t)(r * 64 + ((ch * 4) ^ ((r & 7) << 2))) * 4;
        cp16(dst, KB + (size_t)(q0 + r) * 256 + ch * 8);
    }
    #pragma unroll
    for (int i = 0; i < 4; ++i) {
        int slot = tid + i * 256, r = slot >> 4, ch = slot & 15;
        uint32_t dst = sV + (uint32_t)(r * 64 + ((ch * 4) ^ ((r & 7) << 2))) * 4;
        cp16(dst, KB + (size_t)(s0 + r) * 256 + 128 + ch * 8);
    }
    cp_commit();

    float o[2][16][4] = {};
    float psum[2][2] = {};
    const int rb0 = w * 32;

    for (int kt = 0; kt < 8; ++kt) {
        cp_wait0();
        __syncthreads();
        if (kt < 7) {
            int n0 = s0 + (kt + 1) * 64;
            uint32_t dstb = sV + (uint32_t)(((kt + 1) & 1) * 4096) * 4;
            #pragma unroll
            for (int i = 0; i < 4; ++i) {
                int slot = tid + i * 256, r = slot >> 4, ch = slot & 15;
                uint32_t dst = dstb + (uint32_t)(r * 64 + ((ch * 4) ^ ((r & 7) << 2))) * 4;
                cp16(dst, KB + (size_t)(n0 + r) * 256 + 128 + ch * 8);
            }
            cp_commit();
        }
        const uint32_t vb = sV + (uint32_t)((kt & 1) * 4096) * 4;

        float s[2][8][4] = {};
        #pragma unroll
        for (int ks = 0; ks < 8; ++ks) {
            uint32_t a[2][4];
            #pragma unroll
            for (int mt = 0; mt < 2; ++mt) {
                int row = rb0 + mt * 16 + ((mat & 1) << 3) + mi;
                uint32_t addr = sKq + (uint32_t)(row * 64) * 4
                              + ((((uint32_t)(ks * 2 + (mat >> 1)) * 4) ^ swz) * 4);
                ldmx4(a[mt][0], a[mt][1], a[mt][2], a[mt][3], addr);
            }
            #pragma unroll
            for (int np = 0; np < 4; ++np) {
                int row = np * 16 + ((mat >> 1) << 3) + mi;
                uint32_t addr = vb + (uint32_t)(row * 64) * 4
                              + ((((uint32_t)(ks * 2 + (mat & 1)) * 4) ^ swz) * 4);
                uint32_t b0, b1, b2, b3;
                ldmx4(b0, b1, b2, b3, addr);
                mma16h(s[0][2 * np],     a[0], b0, b1);
                mma16h(s[0][2 * np + 1], a[0], b2, b3);
                mma16h(s[1][2 * np],     a[1], b0, b1);
                mma16h(s[1][2 * np + 1], a[1], b2, b3);
            }
        }

        uint32_t pa[2][4][4];
        #pragma unroll
        for (int mt = 0; mt < 2; ++mt) {
            #pragma unroll
            for (int nt = 0; nt < 8; ++nt) {
                float p0 = ex2(s[mt][nt][0]);
                float p1 = ex2(s[mt][nt][1]);
                float p2 = ex2(s[mt][nt][2]);
                float p3 = ex2(s[mt][nt][3]);
                psum[mt][0] += p0 + p1;
                psum[mt][1] += p2 + p3;
                uint32_t h01 = h2u(__float22half2_rn(make_float2(p0, p1)));
                uint32_t h23 = h2u(__float22half2_rn(make_float2(p2, p3)));
                int kp = nt >> 1;
                if ((nt & 1) == 0) { pa[mt][kp][0] = h01; pa[mt][kp][1] = h23; }
                else               { pa[mt][kp][2] = h01; pa[mt][kp][3] = h23; }
            }
        }

        #pragma unroll
        for (int kp = 0; kp < 4; ++kp) {
            #pragma unroll
            for (int dt2 = 0; dt2 < 8; ++dt2) {
                int row = kp * 16 + ((mat & 1) << 3) + mi;
                uint32_t addr = vb + (uint32_t)(row * 64) * 4
                              + ((((uint32_t)(dt2 * 2 + (mat >> 1)) * 4) ^ swz) * 4);
                uint32_t b0, b1, b2, b3;
                ldmx4t(b0, b1, b2, b3, addr);
                mma16h(o[0][dt2 * 2],     pa[0][kp], b0, b1);
                mma16h(o[0][dt2 * 2 + 1], pa[0][kp], b2, b3);
                mma16h(o[1][dt2 * 2],     pa[1][kp], b0, b1);
                mma16h(o[1][dt2 * 2 + 1], pa[1][kp], b2, b3);
            }
        }
    }

    const size_t pbase = ((size_t)kvi * 8 + b) * 2048 + q0;
    #pragma unroll
    for (int mt = 0; mt < 2; ++mt) {
        float l0 = psum[mt][0], l1 = psum[mt][1];
        l0 += __shfl_xor_sync(0xffffffffu, l0, 1);
        l0 += __shfl_xor_sync(0xffffffffu, l0, 2);
        l1 += __shfl_xor_sync(0xffffffffu, l1, 1);
        l1 += __shfl_xor_sync(0xffffffffu, l1, 2);

        int r0 = rb0 + mt * 16 + g;
        int r1 = r0 + 8;
        __half* o0 = g_PO + (pbase + r0) * 128;
        __half* o1 = g_PO + (pbase + r1) * 128;
        #pragma unroll
        for (int dt = 0; dt < 16; ++dt) {
            __half2 v0 = __float22half2_rn(make_float2(o[mt][dt][0], o[mt][dt][1]));
            __half2 v1 = __float22half2_rn(make_float2(o[mt][dt][2], o[mt][dt][3]));
            *reinterpret_cast<__half2*>(o0 + dt * 8 + 2 * t) = v0;
            *reinterpret_cast<__half2*>(o1 + dt * 8 + 2 * t) = v1;
        }
        if (t == 0) {
            g_Pl[pbase + r0] = l0;
            g_Pl[pbase + r1] = l1;
        }
    }
}

// ---------------------------------------------------------------------------
// Kernel 3: split-KV x4 merge, 4 elements per thread (fp16 partials).
// ---------------------------------------------------------------------------
__global__ __launch_bounds__(256) void merge_kernel(float* __restrict__ out)
{
    int idx = blockIdx.x * 256 + threadIdx.x;
    int d4  = idx & 31;
    int row = idx >> 5;
    float l = g_Pl[row] + g_Pl[16384 + row] + g_Pl[32768 + row] + g_Pl[49152 + row];
    float inv = 1.f / l;
    float acc[4] = {};
    #pragma unroll
    for (int k = 0; k < 4; ++k) {
        uint2 u = *reinterpret_cast<const uint2*>(
            g_PO + (size_t)(k * 16384 + row) * 128 + d4 * 4);
        float2 a0 = __half22float2(*reinterpret_cast<__half2*>(&u.x));
        float2 a1 = __half22float2(*reinterpret_cast<__half2*>(&u.y));
        acc[0] += a0.x; acc[1] += a0.y; acc[2] += a1.x; acc[3] += a1.y;
    }
    float4 v = { acc[0] * inv, acc[1] * inv, acc[2] * inv, acc[3] * inv };
    *reinterpret_cast<float4*>(out + (size_t)row * 128 + d4 * 4) = v;
}

// ---------------------------------------------------------------------------
// Launch. Inputs: x, w_q, b_q, w_k, b_k, w_v, b_v (w_q/b_q unused).
// ---------------------------------------------------------------------------
extern "C" void kernel_launch(void* const* d_in, const int* in_sizes, int n_in,
                              void* d_out, int out_size)
{
    const float* x  = (const float*)d_in[0];
    const float* wk = (const float*)d_in[3];
    const float* bk = (const float*)d_in[4];
    const float* wv = (const float*)d_in[5];
    const float* bv = (const float*)d_in[6];
    float* out = (float*)d_out;
    (void)in_sizes; (void)n_in; (void)out_size;

    const int ATTN_SMEM = (16384 + 2 * 4096) * 4;   // 98304 B
    cudaFuncSetAttribute(kv_gemm_kernel,
                         cudaFuncAttributeMaxDynamicSharedMemorySize, GEMM_SMEM_BYTES);
    cudaFuncSetAttribute(attn_kernel,
                         cudaFuncAttributeMaxDynamicSharedMemorySize, ATTN_SMEM);

    convert_kernel<<<128, 256>>>(wk, wv);
    kv_gemm_kernel<<<dim3(2, 128), 256, GEMM_SMEM_BYTES>>>(x, bk, bv);
    attn_kernel<<<dim3(8, 4, 8), 256, ATTN_SMEM>>>();
    merge_kernel<<<2048, 256>>>(out);
}

// round 17
// speedup vs baseline: 2.0995x; 2.0995x over previous
#include <cuda_runtime.h>
#include <cuda_fp16.h>
#include <math_constants.h>
#include <cstdint>

// Pre-converted W (fp16). X is converted inside the gemm.
static __device__ __align__(16) __half g_Wh[256 * 1024];
// K|V projections, fp16: [B*N, 256]. K cols 0..127 pre-scaled by scale*log2e.
static __device__ __align__(16) __half g_KV[8 * 2048 * 256];
// Split-KV x2 partials: O~ in fp16, l in fp32.
static __device__ __align__(16) __half g_PO[2 * 8 * 2048 * 128];
static __device__ float g_Pl[2 * 8 * 2048];

// ---------------------------------------------------------------------------
// helpers
// ---------------------------------------------------------------------------
__device__ __forceinline__ float ex2(float v) {
    float r; asm("ex2.approx.f32 %0, %1;" : "=f"(r) : "f"(v));
    return r;
}
__device__ __forceinline__ void mma16h(float c[4], const uint32_t a[4],
                                       uint32_t b0, uint32_t b1) {
    asm volatile(
        "mma.sync.aligned.m16n8k16.row.col.f32.f16.f16.f32 "
        "{%0,%1,%2,%3}, {%4,%5,%6,%7}, {%8,%9}, {%0,%1,%2,%3};\n"
        : "+f"(c[0]), "+f"(c[1]), "+f"(c[2]), "+f"(c[3])
        : "r"(a[0]), "r"(a[1]), "r"(a[2]), "r"(a[3]), "r"(b0), "r"(b1));
}
__device__ __forceinline__ void ldmx4(uint32_t& r0, uint32_t& r1, uint32_t& r2,
                                      uint32_t& r3, uint32_t addr) {
    asm volatile("ldmatrix.sync.aligned.m8n8.x4.shared.b16 {%0,%1,%2,%3}, [%4];"
                 : "=r"(r0), "=r"(r1), "=r"(r2), "=r"(r3) : "r"(addr));
}
__device__ __forceinline__ void ldmx4t(uint32_t& r0, uint32_t& r1, uint32_t& r2,
                                       uint32_t& r3, uint32_t addr) {
    asm volatile("ldmatrix.sync.aligned.m8n8.x4.trans.shared.b16 {%0,%1,%2,%3}, [%4];"
                 : "=r"(r0), "=r"(r1), "=r"(r2), "=r"(r3) : "r"(addr));
}
__device__ __forceinline__ void cp16(uint32_t dst, const void* src) {
    asm volatile("cp.async.cg.shared.global [%0], [%1], 16;\n" :: "r"(dst), "l"(src));
}
__device__ __forceinline__ void cp_commit() { asm volatile("cp.async.commit_group;\n"); }
__device__ __forceinline__ void cp_wait0()  { asm volatile("cp.async.wait_group 0;\n"); }
__device__ __forceinline__ void cp_wait1()  { asm volatile("cp.async.wait_group 1;\n"); }

__device__ __forceinline__ uint32_t smem_u32(const void* p) {
    return (uint32_t)__cvta_generic_to_shared(p);
}
__device__ __forceinline__ uint32_t h2u(__half2 h) {
    return *reinterpret_cast<uint32_t*>(&h);
}

// ---------------------------------------------------------------------------
// Kernel 0: convert W -> fp16 (1 MB read).
// ---------------------------------------------------------------------------
__global__ __launch_bounds__(256) void convert_kernel(
    const float* __restrict__ wk, const float* __restrict__ wv)
{
    int wi = (blockIdx.x * 256 + threadIdx.x) * 8;
    int row = wi >> 10, col = wi & 1023;
    const float* src = (row < 128) ? wk + (size_t)row * 1024 + col
                                   : wv + (size_t)(row - 128) * 1024 + col;
    float4 v0 = *reinterpret_cast<const float4*>(src);
    float4 v1 = *reinterpret_cast<const float4*>(src + 4);
    uint4 H;
    H.x = h2u(__float22half2_rn(make_float2(v0.x, v0.y)));
    H.y = h2u(__float22half2_rn(make_float2(v0.z, v0.w)));
    H.z = h2u(__float22half2_rn(make_float2(v1.x, v1.y)));
    H.w = h2u(__float22half2_rn(make_float2(v1.z, v1.w)));
    *reinterpret_cast<uint4*>(g_Wh + wi) = H;
}

// ---------------------------------------------------------------------------
// Kernel 1: KV projection with fused X fp32->fp16 conversion (R15 winner).
// ---------------------------------------------------------------------------
static constexpr int GP        = 20;
static constexpr int XFP       = 36;
static constexpr int XF_WORDS  = 128 * XFP;
static constexpr int XH_OFF    = 3 * XF_WORDS;
static constexpr int XH_WORDS  = 128 * GP;
static constexpr int W_OFF     = XH_OFF + 2 * XH_WORDS;
static constexpr int W_WORDS   = 128 * GP;
static constexpr int GEMM_SMEM_BYTES = (W_OFF + 3 * W_WORDS) * 4;   // 106496

__global__ __launch_bounds__(256, 2) void kv_gemm_kernel(
    const float* __restrict__ x,
    const float* __restrict__ bk, const float* __restrict__ bv)
{
    extern __shared__ uint32_t su[];
    const uint32_t sb = smem_u32(su);
    const int j0 = blockIdx.x * 128;
    const int m0 = blockIdx.y * 128;
    const int tid  = threadIdx.x;
    const int lane = tid & 31;
    const int w    = tid >> 5;
    const int wm   = w & 3;
    const int wn   = w >> 2;
    const int g    = lane >> 2;
    const int t    = lane & 3;
    const int mat  = lane >> 3;
    const int mi   = lane & 7;

    auto fill = [&](int stage, int k0) {
        const uint32_t xf = sb + (uint32_t)(stage * XF_WORDS) * 4;
        #pragma unroll
        for (int i = 0; i < 4; ++i) {
            int slot = tid + i * 256, r = slot >> 3, c4 = slot & 7;
            cp16(xf + (uint32_t)(r * XFP + c4 * 4) * 4,
                 x + (size_t)(m0 + r) * 1024 + k0 + c4 * 4);
        }
        const uint32_t wb = sb + (uint32_t)(W_OFF + stage * W_WORDS) * 4;
        #pragma unroll
        for (int i = 0; i < 2; ++i) {
            int slot = tid + i * 256, r = slot >> 2, c = slot & 3;
            cp16(wb + (uint32_t)(r * GP + c * 4) * 4,
                 g_Wh + (size_t)(j0 + r) * 1024 + k0 + c * 8);
        }
        cp_commit();
    };

    auto cvt = [&](int stage, int buf) {
        const float* xf = reinterpret_cast<const float*>(su) + stage * XF_WORDS;
        uint32_t* xh = su + XH_OFF + buf * XH_WORDS;
        #pragma unroll
        for (int i = 0; i < 4; ++i) {
            int slot = tid + i * 256, r = slot >> 3, c4 = slot & 7;
            float4 v = *reinterpret_cast<const float4*>(xf + r * XFP + c4 * 4);
            uint2 H;
            H.x = h2u(__float22half2_rn(make_float2(v.x, v.y)));
            H.y = h2u(__float22half2_rn(make_float2(v.z, v.w)));
            *reinterpret_cast<uint2*>(xh + r * GP + c4 * 2) = H;
        }
    };

    fill(0, 0);
    fill(1, 32);
    cp_wait1();
    cvt(0, 0);
    __syncthreads();

    float acc[2][8][4] = {};

    for (int kt = 0; kt < 32; ++kt) {
        if (kt + 2 < 32) fill((kt + 2) % 3, (kt + 2) * 32);
        if (kt + 1 < 32) {
            if (kt + 2 < 32) cp_wait1(); else cp_wait0();
            cvt((kt + 1) % 3, (kt + 1) & 1);
        }

        const uint32_t xh  = sb + (uint32_t)(XH_OFF + (kt & 1) * XH_WORDS) * 4;
        const uint32_t whb = sb + (uint32_t)(W_OFF + (kt % 3) * W_WORDS) * 4;

        #pragma unroll
        for (int ks = 0; ks < 2; ++ks) {
            const int kca = ks * 8 + (mat >> 1) * 4;
            const int kcb = ks * 8 + (mat & 1) * 4;
            uint32_t a[2][4];
            #pragma unroll
            for (int mt = 0; mt < 2; ++mt) {
                int row = wm * 32 + mt * 16 + ((mat & 1) << 3) + mi;
                ldmx4(a[mt][0], a[mt][1], a[mt][2], a[mt][3],
                      xh + (uint32_t)(row * GP + kca) * 4);
            }
            #pragma unroll
            for (int np = 0; np < 4; ++np) {
                int row = wn * 64 + np * 16 + ((mat >> 1) << 3) + mi;
                uint32_t h0, h1, h2, h3;
                ldmx4(h0, h1, h2, h3, whb + (uint32_t)(row * GP + kcb) * 4);
                #pragma unroll
                for (int mt = 0; mt < 2; ++mt) {
                    mma16h(acc[mt][2 * np],     a[mt], h0, h1);
                    mma16h(acc[mt][2 * np + 1], a[mt], h2, h3);
                }
            }
        }
        __syncthreads();
    }

    const float SCL = 0.08838834764831845f * 1.4426950408889634f;
    #pragma unroll
    for (int mt = 0; mt < 2; ++mt) {
        int r0 = m0 + wm * 32 + mt * 16 + g;
        int r1 = r0 + 8;
        #pragma unroll
        for (int nt = 0; nt < 8; ++nt) {
            int col = j0 + wn * 64 + nt * 8 + 2 * t;
            bool isK = (col < 128);
            float b0 = isK ? bk[col]     : bv[col - 128];
            float b1 = isK ? bk[col + 1] : bv[col + 1 - 128];
            float v00 = acc[mt][nt][0] + b0, v01 = acc[mt][nt][1] + b1;
            float v10 = acc[mt][nt][2] + b0, v11 = acc[mt][nt][3] + b1;
            if (isK) { v00 *= SCL; v01 *= SCL; v10 *= SCL; v11 *= SCL; }
            __half2 h0 = __float22half2_rn(make_float2(v00, v01));
            __half2 h1 = __float22half2_rn(make_float2(v10, v11));
            *reinterpret_cast<__half2*>(g_KV + (size_t)r0 * 256 + col) = h0;
            *reinterpret_cast<__half2*>(g_KV + (size_t)r1 * 256 + col) = h1;
        }
    }
}

// ---------------------------------------------------------------------------
// Kernel 2: fused flash attention (R11/R15 internals; V now TRIPLE-buffered
// with commit-depth 2 so the next tile's cp.async is always in flight before
// the barrier). Split-KV x2, 256 threads, 1 CTA/SM (no reg pressure change).
// ---------------------------------------------------------------------------
__global__ __launch_bounds__(256, 1) void attn_kernel()
{
    extern __shared__ uint32_t su[];
    const int q0  = blockIdx.x * 256;
    const int kvi = blockIdx.y;
    const int b   = blockIdx.z;
    const int s0  = kvi * 1024;
    const __half* KB = g_KV + (size_t)b * 2048 * 256;
    const int tid  = threadIdx.x;
    const int lane = tid & 31;
    const int w    = tid >> 5;
    const int g    = lane >> 2;
    const int t    = lane & 3;
    const int mat  = lane >> 3;
    const int mi   = lane & 7;
    const uint32_t swz = (uint32_t)mi << 2;

    const uint32_t sKq = smem_u32(su);
    const uint32_t sV  = sKq + 16384 * 4;      // 3 x (64 rows x 64 words)

    auto fillV = [&](int tile) {
        int n0 = s0 + tile * 64;
        uint32_t dstb = sV + (uint32_t)((tile % 3) * 4096) * 4;
        #pragma unroll
        for (int i = 0; i < 4; ++i) {
            int slot = tid + i * 256, r = slot >> 4, ch = slot & 15;
            uint32_t dst = dstb + (uint32_t)(r * 64 + ((ch * 4) ^ ((r & 7) << 2))) * 4;
            cp16(dst, KB + (size_t)(n0 + r) * 256 + 128 + ch * 8);
        }
        cp_commit();
    };

    // prologue: Kq + V tile 0 (group 0), V tile 1 (group 1)
    #pragma unroll
    for (int i = 0; i < 16; ++i) {
        int slot = tid + i * 256, r = slot >> 4, ch = slot & 15;
        uint32_t dst = sKq + (uint32_t)(r * 64 + ((ch * 4) ^ ((r & 7) << 2))) * 4;
        cp16(dst, KB + (size_t)(q0 + r) * 256 + ch * 8);
    }
    fillV(0);
    fillV(1);

    float o[2][16][4] = {};
    float psum[2][2] = {};
    const int rb0 = w * 32;

    for (int kt = 0; kt < 16; ++kt) {
        if (kt < 15) cp_wait1(); else cp_wait0();   // fill(kt) landed
        __syncthreads();                            // prev reads of buf (kt+2)%3 done
        if (kt + 2 < 16) fillV(kt + 2);
        const uint32_t vb = sV + (uint32_t)((kt % 3) * 4096) * 4;

        float s[2][8][4] = {};
        #pragma unroll
        for (int ks = 0; ks < 8; ++ks) {
            uint32_t a[2][4];
            #pragma unroll
            for (int mt = 0; mt < 2; ++mt) {
                int row = rb0 + mt * 16 + ((mat & 1) << 3) + mi;
                uint32_t addr = sKq + (uint32_t)(row * 64) * 4
                              + ((((uint32_t)(ks * 2 + (mat >> 1)) * 4) ^ swz) * 4);
                ldmx4(a[mt][0], a[mt][1], a[mt][2], a[mt][3], addr);
            }
            #pragma unroll
            for (int np = 0; np < 4; ++np) {
                int row = np * 16 + ((mat >> 1) << 3) + mi;
                uint32_t addr = vb + (uint32_t)(row * 64) * 4
                              + ((((uint32_t)(ks * 2 + (mat & 1)) * 4) ^ swz) * 4);
                uint32_t b0, b1, b2, b3;
                ldmx4(b0, b1, b2, b3, addr);
                mma16h(s[0][2 * np],     a[0], b0, b1);
                mma16h(s[0][2 * np + 1], a[0], b2, b3);
                mma16h(s[1][2 * np],     a[1], b0, b1);
                mma16h(s[1][2 * np + 1], a[1], b2, b3);
            }
        }

        uint32_t pa[2][4][4];
        #pragma unroll
        for (int mt = 0; mt < 2; ++mt) {
            #pragma unroll
            for (int nt = 0; nt < 8; ++nt) {
                float p0 = ex2(s[mt][nt][0]);
                float p1 = ex2(s[mt][nt][1]);
                float p2 = ex2(s[mt][nt][2]);
                float p3 = ex2(s[mt][nt][3]);
                psum[mt][0] += p0 + p1;
                psum[mt][1] += p2 + p3;
                uint32_t h01 = h2u(__float22half2_rn(make_float2(p0, p1)));
                uint32_t h23 = h2u(__float22half2_rn(make_float2(p2, p3)));
                int kp = nt >> 1;
                if ((nt & 1) == 0) { pa[mt][kp][0] = h01; pa[mt][kp][1] = h23; }
                else               { pa[mt][kp][2] = h01; pa[mt][kp][3] = h23; }
            }
        }

        #pragma unroll
        for (int kp = 0; kp < 4; ++kp) {
            #pragma unroll
            for (int dt2 = 0; dt2 < 8; ++dt2) {
                int row = kp * 16 + ((mat & 1) << 3) + mi;
                uint32_t addr = vb + (uint32_t)(row * 64) * 4
                              + ((((uint32_t)(dt2 * 2 + (mat >> 1)) * 4) ^ swz) * 4);
                uint32_t b0, b1, b2, b3;
                ldmx4t(b0, b1, b2, b3, addr);
                mma16h(o[0][dt2 * 2],     pa[0][kp], b0, b1);
                mma16h(o[0][dt2 * 2 + 1], pa[0][kp], b2, b3);
                mma16h(o[1][dt2 * 2],     pa[1][kp], b0, b1);
                mma16h(o[1][dt2 * 2 + 1], pa[1][kp], b2, b3);
            }
        }
    }

    const size_t pbase = ((size_t)kvi * 8 + b) * 2048 + q0;
    #pragma unroll
    for (int mt = 0; mt < 2; ++mt) {
        float l0 = psum[mt][0], l1 = psum[mt][1];
        l0 += __shfl_xor_sync(0xffffffffu, l0, 1);
        l0 += __shfl_xor_sync(0xffffffffu, l0, 2);
        l1 += __shfl_xor_sync(0xffffffffu, l1, 1);
        l1 += __shfl_xor_sync(0xffffffffu, l1, 2);

        int r0 = rb0 + mt * 16 + g;
        int r1 = r0 + 8;
        __half* o0 = g_PO + (pbase + r0) * 128;
        __half* o1 = g_PO + (pbase + r1) * 128;
        #pragma unroll
        for (int dt = 0; dt < 16; ++dt) {
            __half2 v0 = __float22half2_rn(make_float2(o[mt][dt][0], o[mt][dt][1]));
            __half2 v1 = __float22half2_rn(make_float2(o[mt][dt][2], o[mt][dt][3]));
            *reinterpret_cast<__half2*>(o0 + dt * 8 + 2 * t) = v0;
            *reinterpret_cast<__half2*>(o1 + dt * 8 + 2 * t) = v1;
        }
        if (t == 0) {
            g_Pl[pbase + r0] = l0;
            g_Pl[pbase + r1] = l1;
        }
    }
}

// ---------------------------------------------------------------------------
// Kernel 3: split-KV x2 merge, 4 elements per thread (fp16 partials).
// ---------------------------------------------------------------------------
__global__ __launch_bounds__(256) void merge_kernel(float* __restrict__ out)
{
    int idx = blockIdx.x * 256 + threadIdx.x;
    int d4  = idx & 31;
    int row = idx >> 5;
    float l  = g_Pl[row] + g_Pl[16384 + row];
    float inv = 1.f / l;
    uint2 u0 = *reinterpret_cast<const uint2*>(g_PO + (size_t)row * 128 + d4 * 4);
    uint2 u1 = *reinterpret_cast<const uint2*>(g_PO + (size_t)(16384 + row) * 128 + d4 * 4);
    float2 a0 = __half22float2(*reinterpret_cast<__half2*>(&u0.x));
    float2 a1 = __half22float2(*reinterpret_cast<__half2*>(&u0.y));
    float2 b0 = __half22float2(*reinterpret_cast<__half2*>(&u1.x));
    float2 b1 = __half22float2(*reinterpret_cast<__half2*>(&u1.y));
    float4 v;
    v.x = (a0.x + b0.x) * inv;
    v.y = (a0.y + b0.y) * inv;
    v.z = (a1.x + b1.x) * inv;
    v.w = (a1.y + b1.y) * inv;
    *reinterpret_cast<float4*>(out + (size_t)row * 128 + d4 * 4) = v;
}

// ---------------------------------------------------------------------------
// Launch. Inputs: x, w_q, b_q, w_k, b_k, w_v, b_v (w_q/b_q unused).
// ---------------------------------------------------------------------------
extern "C" void kernel_launch(void* const* d_in, const int* in_sizes, int n_in,
                              void* d_out, int out_size)
{
    const float* x  = (const float*)d_in[0];
    const float* wk = (const float*)d_in[3];
    const float* bk = (const float*)d_in[4];
    const float* wv = (const float*)d_in[5];
    const float* bv = (const float*)d_in[6];
    float* out = (float*)d_out;
    (void)in_sizes; (void)n_in; (void)out_size;

    const int ATTN_SMEM = (16384 + 3 * 4096) * 4;   // 114688 B
    cudaFuncSetAttribute(kv_gemm_kernel,
                         cudaFuncAttributeMaxDynamicSharedMemorySize, GEMM_SMEM_BYTES);
    cudaFuncSetAttribute(attn_kernel,
                         cudaFuncAttributeMaxDynamicSharedMemorySize, ATTN_SMEM);

    convert_kernel<<<128, 256>>>(wk, wv);
    kv_gemm_kernel<<<dim3(2, 128), 256, GEMM_SMEM_BYTES>>>(x, bk, bv);
    attn_kernel<<<dim3(8, 2, 8), 256, ATTN_SMEM>>>();
    merge_kernel<<<2048, 256>>>(out);
}